// round 2
// baseline (speedup 1.0000x reference)
#include <cuda_runtime.h>
#include <math.h>

#define NTOK 8192
#define DIM  1024
#define NEXP 8

// ---- device scratch (alloc-free rule: __device__ globals) ----
__device__ int   g_eid[NTOK];
__device__ float g_w[NTOK];
__device__ int   g_counts[NEXP];
__device__ int   g_offs[NEXP];
__device__ int   g_fill[NEXP];
__device__ int   g_perm[NTOK];
__device__ float g_h[(size_t)NTOK * DIM];   // 32 MB intermediate (grouped rows)

// ---------------------------------------------------------------------------
__global__ void init_kernel() {
    int t = threadIdx.x;
    if (t < NEXP) g_counts[t] = 0;
}

// One warp per token: logits = x@Wg + bg, softmax, argmax, weight.
__global__ void gate_kernel(const float* __restrict__ x,
                            const float* __restrict__ Wg,
                            const float* __restrict__ bg) {
    int warp = (blockIdx.x * blockDim.x + threadIdx.x) >> 5;
    int lane = threadIdx.x & 31;
    if (warp >= NTOK) return;
    const float* xr = x + (size_t)warp * DIM;
    float acc[NEXP];
#pragma unroll
    for (int e = 0; e < NEXP; e++) acc[e] = 0.f;
    for (int d = lane; d < DIM; d += 32) {
        float xv = xr[d];
        const float* wr = Wg + d * NEXP;
#pragma unroll
        for (int e = 0; e < NEXP; e++) acc[e] = fmaf(xv, wr[e], acc[e]);
    }
#pragma unroll
    for (int e = 0; e < NEXP; e++) {
#pragma unroll
        for (int o = 16; o > 0; o >>= 1)
            acc[e] += __shfl_xor_sync(0xffffffffu, acc[e], o);
    }
    if (lane == 0) {
        float l[NEXP];
        float best = -1e30f; int bi = 0;
#pragma unroll
        for (int e = 0; e < NEXP; e++) {
            l[e] = acc[e] + bg[e];
            if (l[e] > best) { best = l[e]; bi = e; }   // first-max, matches jnp.argmax
        }
        float s = 0.f;
#pragma unroll
        for (int e = 0; e < NEXP; e++) s += expf(l[e] - best);
        g_eid[warp] = bi;
        g_w[warp]   = 1.0f / s;      // prob of argmax expert
        atomicAdd(&g_counts[bi], 1);
    }
}

__global__ void scan_kernel() {
    if (threadIdx.x == 0) {
        int o = 0;
        for (int e = 0; e < NEXP; e++) {
            g_offs[e] = o;
            g_fill[e] = o;
            o += g_counts[e];
        }
    }
}

__global__ void scatter_kernel() {
    int t = blockIdx.x * blockDim.x + threadIdx.x;
    if (t < NTOK) {
        int pos = atomicAdd(&g_fill[g_eid[t]], 1);
        g_perm[pos] = t;
    }
}

// ---------------------------------------------------------------------------
// Grouped GEMM: per expert e, rows = tokens assigned to e.
// STAGE 1: A = x rows via perm,  B = W1[e],  out = gelu(A@B + b1[e]) -> g_h (grouped)
// STAGE 2: A = g_h (contiguous), B = W2[e],  out[token] = w_tok*(A@B + b2[e])
#define BM 128
#define BN 128
#define BK 8
#define TM 8
#define TN 8

template <int STAGE>
__global__ void __launch_bounds__(256)
gemm_kernel(const float* __restrict__ x,
            const float* __restrict__ W,
            const float* __restrict__ Bias,
            float* __restrict__ out) {
    __shared__ float As[BK][BM];
    __shared__ float Bs[BK][BN];

    const int e   = blockIdx.z;
    const int cnt = g_counts[e];
    const int m0  = blockIdx.y * BM;
    if (m0 >= cnt) return;
    const int off = g_offs[e];
    const int n0  = blockIdx.x * BN;

    const float* Wb = W + (size_t)e * DIM * DIM;

    const int tid  = threadIdx.x;
    const int arow = tid >> 1;            // 0..127
    const int acol = (tid & 1) * 4;       // 0 or 4
    const int brow = tid >> 5;            // 0..7
    const int bcol = (tid & 31) * 4;      // 0..124

    const bool avalid = (m0 + arow) < cnt;
    const int  grow   = off + (avalid ? (m0 + arow) : 0);
    const float* arow_ptr;
    if (STAGE == 1) {
        arow_ptr = x + (size_t)g_perm[grow] * DIM;
    } else {
        arow_ptr = g_h + (size_t)grow * DIM;
    }

    const int tx = tid & 15, ty = tid >> 4;

    float acc[TM][TN];
#pragma unroll
    for (int i = 0; i < TM; i++)
#pragma unroll
        for (int j = 0; j < TN; j++) acc[i][j] = 0.f;

    for (int k0 = 0; k0 < DIM; k0 += BK) {
        float4 av = avalid ? *(const float4*)(arow_ptr + k0 + acol)
                           : make_float4(0.f, 0.f, 0.f, 0.f);
        As[acol + 0][arow] = av.x;
        As[acol + 1][arow] = av.y;
        As[acol + 2][arow] = av.z;
        As[acol + 3][arow] = av.w;
        *(float4*)&Bs[brow][bcol] =
            *(const float4*)(Wb + (size_t)(k0 + brow) * DIM + n0 + bcol);
        __syncthreads();

#pragma unroll
        for (int k = 0; k < BK; k++) {
            float a[TM], b[TN];
            float4 a0 = *(const float4*)&As[k][ty * TM];
            float4 a1 = *(const float4*)&As[k][ty * TM + 4];
            a[0]=a0.x; a[1]=a0.y; a[2]=a0.z; a[3]=a0.w;
            a[4]=a1.x; a[5]=a1.y; a[6]=a1.z; a[7]=a1.w;
            float4 b0 = *(const float4*)&Bs[k][tx * TN];
            float4 b1v = *(const float4*)&Bs[k][tx * TN + 4];
            b[0]=b0.x; b[1]=b0.y; b[2]=b0.z; b[3]=b0.w;
            b[4]=b1v.x; b[5]=b1v.y; b[6]=b1v.z; b[7]=b1v.w;
#pragma unroll
            for (int i = 0; i < TM; i++)
#pragma unroll
                for (int j = 0; j < TN; j++)
                    acc[i][j] = fmaf(a[i], b[j], acc[i][j]);
        }
        __syncthreads();
    }

    // epilogue
#pragma unroll
    for (int i = 0; i < TM; i++) {
        int row = m0 + ty * TM + i;
        if (row >= cnt) continue;
        int grow2 = off + row;
        int ncol  = n0 + tx * TN;
        if (STAGE == 1) {
            float* orow = g_h + (size_t)grow2 * DIM + ncol;
#pragma unroll
            for (int j = 0; j < TN; j++) {
                float v = acc[i][j] + Bias[e * DIM + ncol + j];
                // exact GELU: 0.5*v*(1+erf(v/sqrt(2)))
                orow[j] = 0.5f * v * (1.0f + erff(v * 0.70710678118654752f));
            }
        } else {
            int tok = g_perm[grow2];
            float wt = g_w[tok];
            float* orow = out + (size_t)tok * DIM + ncol;
#pragma unroll
            for (int j = 0; j < TN; j++) {
                float v = acc[i][j] + Bias[e * DIM + ncol + j];
                orow[j] = wt * v;
            }
        }
    }
}

// ---------------------------------------------------------------------------
extern "C" void kernel_launch(void* const* d_in, const int* in_sizes, int n_in,
                              void* d_out, int out_size) {
    const float* x  = (const float*)d_in[0];
    const float* Wg = (const float*)d_in[1];
    const float* bg = (const float*)d_in[2];
    const float* W1 = (const float*)d_in[3];
    const float* b1 = (const float*)d_in[4];
    const float* W2 = (const float*)d_in[5];
    const float* b2 = (const float*)d_in[6];
    float* out = (float*)d_out;

    init_kernel<<<1, 32>>>();
    gate_kernel<<<(NTOK * 32 + 255) / 256, 256>>>(x, Wg, bg);
    scan_kernel<<<1, 32>>>();
    scatter_kernel<<<(NTOK + 255) / 256, 256>>>();

    dim3 grid(DIM / BN, NTOK / BM, NEXP);   // most (expert, mtile) blocks early-exit
    gemm_kernel<1><<<grid, 256>>>(x, W1, b1, nullptr);
    gemm_kernel<2><<<grid, 256>>>(nullptr, W2, b2, out);
}

// round 5
// speedup vs baseline: 2.4121x; 2.4121x over previous
#include <cuda_runtime.h>
#include <math.h>
#include <stdint.h>

#define NTOK 8192
#define DIM  1024
#define NEXP 8
#define BM   128
#define BN   128
#define BK   32
#define PADROWS (NTOK + NEXP*128)     // 9216 worst-case padded rows
#define PADTILES (PADROWS / 128)      // 72

// ---------------- device scratch (alloc-free rule) ----------------
__device__ int   g_eid[NTOK];
__device__ float g_w[NTOK];
__device__ int   g_counts[NEXP];
__device__ int   g_offs[NEXP];        // padded group start offsets (multiples of 128)
__device__ int   g_fill[NEXP];
__device__ int   g_padcnt[NEXP];      // ceil(cnt/128)*128
__device__ int   g_pperm[PADROWS];    // padded pos -> token (or -1)
// k-major blocked: [tile][k][128 rows]
__device__ float g_xp[(size_t)PADTILES * DIM * 128];
__device__ float g_h [(size_t)PADTILES * DIM * 128];

__device__ __forceinline__ float to_tf32(float v) {
    float r; asm("cvt.rna.tf32.f32 %0, %1;" : "=f"(r) : "f"(v)); return r;
}

// ---------------- small kernels ----------------
__global__ void init_kernel() {
    int t = threadIdx.x;
    if (t < NEXP) g_counts[t] = 0;
}

__global__ void gate_kernel(const float* __restrict__ x,
                            const float* __restrict__ Wg,
                            const float* __restrict__ bg) {
    int warp = (blockIdx.x * blockDim.x + threadIdx.x) >> 5;
    int lane = threadIdx.x & 31;
    if (warp >= NTOK) return;
    const float* xr = x + (size_t)warp * DIM;
    float acc[NEXP];
#pragma unroll
    for (int e = 0; e < NEXP; e++) acc[e] = 0.f;
    for (int d = lane; d < DIM; d += 32) {
        float xv = xr[d];
        const float* wr = Wg + d * NEXP;
#pragma unroll
        for (int e = 0; e < NEXP; e++) acc[e] = fmaf(xv, wr[e], acc[e]);
    }
#pragma unroll
    for (int e = 0; e < NEXP; e++) {
#pragma unroll
        for (int o = 16; o > 0; o >>= 1)
            acc[e] += __shfl_xor_sync(0xffffffffu, acc[e], o);
    }
    if (lane == 0) {
        float l[NEXP];
        float best = -1e30f; int bi = 0;
#pragma unroll
        for (int e = 0; e < NEXP; e++) {
            l[e] = acc[e] + bg[e];
            if (l[e] > best) { best = l[e]; bi = e; }   // first-max, matches jnp.argmax
        }
        float s = 0.f;
#pragma unroll
        for (int e = 0; e < NEXP; e++) s += expf(l[e] - best);
        g_eid[warp] = bi;
        g_w[warp]   = 1.0f / s;
        atomicAdd(&g_counts[bi], 1);
    }
}

__global__ void scan_kernel() {
    if (threadIdx.x == 0) {
        int o = 0;
        for (int e = 0; e < NEXP; e++) {
            int pc = ((g_counts[e] + BM - 1) / BM) * BM;
            g_padcnt[e] = pc;
            g_offs[e] = o;
            g_fill[e] = o;
            o += pc;
        }
    }
}

__global__ void fillp_kernel() {
    int t = blockIdx.x * blockDim.x + threadIdx.x;
    if (t < PADROWS) g_pperm[t] = -1;
}

__global__ void scatter_kernel() {
    int t = blockIdx.x * blockDim.x + threadIdx.x;
    if (t < NTOK) {
        int pos = atomicAdd(&g_fill[g_eid[t]], 1);
        g_pperm[pos] = t;
    }
}

// One block per 128-row tile: transpose x rows (tf32-rounded) into g_xp[tile][k][m].
__global__ void copyxp_kernel(const float* __restrict__ x) {
    __shared__ float sm[32][133];
    const int tile = blockIdx.x;
    const int tid = threadIdx.x;
    const int base = tile * 128;

    for (int kc = 0; kc < DIM / 32; kc++) {
        __syncthreads();
#pragma unroll
        for (int i = 0; i < 4; i++) {
            int task = i * 256 + tid;          // 0..1023
            int m = task >> 3;                 // 0..127
            int c = task & 7;                  // float4 chunk in k
            int tok = g_pperm[base + m];
            float4 v = (tok >= 0)
                ? *(const float4*)(x + (size_t)tok * DIM + kc * 32 + c * 4)
                : make_float4(0.f, 0.f, 0.f, 0.f);
            sm[c * 4 + 0][m] = to_tf32(v.x);
            sm[c * 4 + 1][m] = to_tf32(v.y);
            sm[c * 4 + 2][m] = to_tf32(v.z);
            sm[c * 4 + 3][m] = to_tf32(v.w);
        }
        __syncthreads();
        float* dst = g_xp + (size_t)tile * DIM * 128 + (size_t)kc * 32 * 128;
#pragma unroll
        for (int i = 0; i < 4; i++) {
            int task = i * 256 + tid;
            int k  = task >> 5;                // 0..31
            int ch = (task & 31) * 4;          // 0..124
            float4 o;
            o.x = sm[k][ch + 0]; o.y = sm[k][ch + 1];
            o.z = sm[k][ch + 2]; o.w = sm[k][ch + 3];
            *(float4*)(dst + (size_t)k * 128 + ch) = o;
        }
    }
}

// ---------------- tf32 mma.sync grouped GEMM ----------------
// STAGE 1: A=g_xp (k-major blocked), B=W1[e] ([k][n]) -> g_h = tf32(gelu(A@W1+b1)), k-major blocked
// STAGE 2: A=g_h,  B=W2[e]                          -> out[tok] = w_tok*(A@W2 + b2)
#define MMA_TF32(d, a, b)                                                        \
    asm volatile(                                                                \
        "mma.sync.aligned.m16n8k8.row.col.f32.tf32.tf32.f32 "                    \
        "{%0,%1,%2,%3}, {%4,%5,%6,%7}, {%8,%9}, {%0,%1,%2,%3};"                  \
        : "+f"((d)[0]), "+f"((d)[1]), "+f"((d)[2]), "+f"((d)[3])                 \
        : "r"((a)[0]), "r"((a)[1]), "r"((a)[2]), "r"((a)[3]),                    \
          "r"((b)[0]), "r"((b)[1]))

template <int STAGE>
__global__ void __launch_bounds__(256, 2)
gemm_mma(const float* __restrict__ W, const float* __restrict__ Bias,
         float* __restrict__ out) {
    __shared__ float As[BK][136];
    __shared__ float Bs[BK][136];

    const int e  = blockIdx.z;
    const int m0 = blockIdx.y * BM;
    if (m0 >= g_padcnt[e]) return;
    const int n0   = blockIdx.x * BN;
    const int off  = g_offs[e];
    const int tile = (off + m0) >> 7;

    const float* Abase = (STAGE == 1 ? g_xp : g_h) + (size_t)tile * DIM * 128;
    const float* Bbase = W + (size_t)e * DIM * DIM;

    const int tid  = threadIdx.x;
    const int lane = tid & 31;
    const int wid  = tid >> 5;
    const int wm   = (wid >> 2) * 64;   // 0 or 64
    const int wn   = (wid & 3) * 32;    // 0,32,64,96
    const int g    = lane >> 2;         // 0..7
    const int t4   = lane & 3;          // 0..3

    float acc[4][4][4];
#pragma unroll
    for (int mi = 0; mi < 4; mi++)
#pragma unroll
        for (int nj = 0; nj < 4; nj++)
#pragma unroll
            for (int r = 0; r < 4; r++) acc[mi][nj][r] = 0.f;

    for (int k0 = 0; k0 < DIM; k0 += BK) {
        // ---- stage tiles ----
#pragma unroll
        for (int i = 0; i < 4; i++) {
            int task = i * 256 + tid;           // 0..1023
            int kr = task >> 5;                 // 0..31
            int ch = (task & 31) * 4;           // 0..124
            float4 va = *(const float4*)(Abase + (size_t)(k0 + kr) * 128 + ch);
            *(float4*)&As[kr][ch] = va;         // already tf32-rounded
            float4 vb = *(const float4*)(Bbase + (size_t)(k0 + kr) * DIM + n0 + ch);
            vb.x = to_tf32(vb.x); vb.y = to_tf32(vb.y);
            vb.z = to_tf32(vb.z); vb.w = to_tf32(vb.w);
            *(float4*)&Bs[kr][ch] = vb;
        }
        __syncthreads();

        // ---- compute ----
#pragma unroll
        for (int kk = 0; kk < 4; kk++) {
            const int kb = kk * 8;
            uint32_t a[4][4], b[4][2];
#pragma unroll
            for (int mi = 0; mi < 4; mi++) {
                int m = wm + mi * 16;
                a[mi][0] = __float_as_uint(As[kb + t4    ][m + g    ]);
                a[mi][1] = __float_as_uint(As[kb + t4    ][m + g + 8]);
                a[mi][2] = __float_as_uint(As[kb + t4 + 4][m + g    ]);
                a[mi][3] = __float_as_uint(As[kb + t4 + 4][m + g + 8]);
            }
#pragma unroll
            for (int nj = 0; nj < 4; nj++) {
                int n = wn + nj * 8;
                b[nj][0] = __float_as_uint(Bs[kb + t4    ][n + g]);
                b[nj][1] = __float_as_uint(Bs[kb + t4 + 4][n + g]);
            }
#pragma unroll
            for (int mi = 0; mi < 4; mi++)
#pragma unroll
                for (int nj = 0; nj < 4; nj++)
                    MMA_TF32(acc[mi][nj], a[mi], b[nj]);
        }
        __syncthreads();
    }

    // ---- epilogue ----
    if (STAGE == 1) {
        float* Hbase = g_h + (size_t)tile * DIM * 128;
#pragma unroll
        for (int mi = 0; mi < 4; mi++) {
            int mA = wm + mi * 16 + g;
            int mB = mA + 8;
#pragma unroll
            for (int nj = 0; nj < 4; nj++) {
                int n = n0 + wn + nj * 8 + t4 * 2;
                float bi0 = Bias[e * DIM + n];
                float bi1 = Bias[e * DIM + n + 1];
                float v0 = acc[mi][nj][0] + bi0;
                float v1 = acc[mi][nj][1] + bi1;
                float v2 = acc[mi][nj][2] + bi0;
                float v3 = acc[mi][nj][3] + bi1;
                Hbase[(size_t)n * 128 + mA]       = to_tf32(0.5f * v0 * (1.0f + erff(v0 * 0.70710678118654752f)));
                Hbase[(size_t)(n + 1) * 128 + mA] = to_tf32(0.5f * v1 * (1.0f + erff(v1 * 0.70710678118654752f)));
                Hbase[(size_t)n * 128 + mB]       = to_tf32(0.5f * v2 * (1.0f + erff(v2 * 0.70710678118654752f)));
                Hbase[(size_t)(n + 1) * 128 + mB] = to_tf32(0.5f * v3 * (1.0f + erff(v3 * 0.70710678118654752f)));
            }
        }
    } else {
        const int prow = off + m0;
#pragma unroll
        for (int mi = 0; mi < 4; mi++) {
            int mA = wm + mi * 16 + g;
            int mB = mA + 8;
            int tokA = g_pperm[prow + mA];
            int tokB = g_pperm[prow + mB];
            float wA = (tokA >= 0) ? g_w[tokA] : 0.f;
            float wB = (tokB >= 0) ? g_w[tokB] : 0.f;
#pragma unroll
            for (int nj = 0; nj < 4; nj++) {
                int n = n0 + wn + nj * 8 + t4 * 2;
                float bi0 = Bias[e * DIM + n];
                float bi1 = Bias[e * DIM + n + 1];
                if (tokA >= 0) {
                    out[(size_t)tokA * DIM + n]     = wA * (acc[mi][nj][0] + bi0);
                    out[(size_t)tokA * DIM + n + 1] = wA * (acc[mi][nj][1] + bi1);
                }
                if (tokB >= 0) {
                    out[(size_t)tokB * DIM + n]     = wB * (acc[mi][nj][2] + bi0);
                    out[(size_t)tokB * DIM + n + 1] = wB * (acc[mi][nj][3] + bi1);
                }
            }
        }
    }
}

// ---------------------------------------------------------------------------
extern "C" void kernel_launch(void* const* d_in, const int* in_sizes, int n_in,
                              void* d_out, int out_size) {
    const float* x  = (const float*)d_in[0];
    const float* Wg = (const float*)d_in[1];
    const float* bg = (const float*)d_in[2];
    const float* W1 = (const float*)d_in[3];
    const float* b1 = (const float*)d_in[4];
    const float* W2 = (const float*)d_in[5];
    const float* b2 = (const float*)d_in[6];
    float* out = (float*)d_out;

    init_kernel<<<1, 32>>>();
    gate_kernel<<<(NTOK * 32 + 255) / 256, 256>>>(x, Wg, bg);
    scan_kernel<<<1, 32>>>();
    fillp_kernel<<<(PADROWS + 255) / 256, 256>>>();
    scatter_kernel<<<(NTOK + 255) / 256, 256>>>();
    copyxp_kernel<<<PADTILES, 256>>>(x);

    dim3 grid(DIM / BN, PADTILES, NEXP);   // early-exit beyond each expert's padcnt
    gemm_mma<1><<<grid, 256>>>(W1, b1, nullptr);
    gemm_mma<2><<<grid, 256>>>(W2, b2, out);
}